// round 10
// baseline (speedup 1.0000x reference)
#include <cuda_runtime.h>
#include <cuda_bf16.h>
#include <cstdint>

// ---------------- problem constants ----------------
#define Bb   8
#define Tt   192
#define Nn   64
#define Dd   512
#define Hh   8
#define DH   64
#define Cc   8
#define BT   (Bb * Tt)            // 1536
#define M_ALL (Bb * Tt * Nn)      // 98304

#define SWZ(o) ((o) ^ (((o) >> 3) & 0x70))

// ---------------- scratch ----------------
__device__ __nv_bfloat16 g_Qh[(size_t)M_ALL * Dd], g_Ql[(size_t)M_ALL * Dd];
__device__ __nv_bfloat16 g_Kh[(size_t)M_ALL * Dd], g_Kl[(size_t)M_ALL * Dd];
__device__ __nv_bfloat16 g_Vh[(size_t)M_ALL * Dd], g_Vl[(size_t)M_ALL * Dd];
__device__ __nv_bfloat16 g_xh[(size_t)M_ALL * Dd], g_xl[(size_t)M_ALL * Dd];
__device__ __nv_bfloat16 g_Ah[(size_t)M_ALL * Dd], g_Al[(size_t)M_ALL * Dd];
__device__ __nv_bfloat16 g_wqh[Dd * Dd], g_wql[Dd * Dd];
__device__ __nv_bfloat16 g_wvh[Dd * Dd], g_wvl[Dd * Dd];
__device__ __nv_bfloat16 g_wph[Dd * Dd], g_wpl[Dd * Dd];
__device__ __nv_bfloat16 g_wkth[(size_t)Cc * Dd * Dd], g_wktl[(size_t)Cc * Dd * Dd];
__device__ int g_cid[Nn];

// ---------------- PTX helpers (portable) ----------------
__device__ __forceinline__ uint32_t smem_u32(const void* p) {
    uint32_t a;
    asm("{ .reg .u64 t; cvta.to.shared.u64 t, %1; cvt.u32.u64 %0, t; }" : "=r"(a) : "l"(p));
    return a;
}
#define CP_ASYNC(dst, src) \
    asm volatile("cp.async.cg.shared.global [%0], [%1], 16;" :: "r"(dst), "l"(src))
#define CP_COMMIT() asm volatile("cp.async.commit_group;" ::: "memory")
#define CP_WAIT(n)  asm volatile("cp.async.wait_group %0;" :: "n"(n) : "memory")

#define LDM_X4(r, addr) \
    asm volatile("ldmatrix.sync.aligned.m8n8.x4.shared.b16 {%0,%1,%2,%3}, [%4];" \
        : "=r"((r)[0]), "=r"((r)[1]), "=r"((r)[2]), "=r"((r)[3]) : "r"(addr))

#define LDM_X4T(r, addr) \
    asm volatile("ldmatrix.sync.aligned.m8n8.x4.trans.shared.b16 {%0,%1,%2,%3}, [%4];" \
        : "=r"((r)[0]), "=r"((r)[1]), "=r"((r)[2]), "=r"((r)[3]) : "r"(addr))

#define MMA16816(d, a, b0, b1) \
    asm volatile("mma.sync.aligned.m16n8k16.row.col.f32.bf16.bf16.f32 " \
        "{%0,%1,%2,%3}, {%4,%5,%6,%7}, {%8,%9}, {%0,%1,%2,%3};" \
        : "+f"((d)[0]), "+f"((d)[1]), "+f"((d)[2]), "+f"((d)[3]) \
        : "r"((a)[0]), "r"((a)[1]), "r"((a)[2]), "r"((a)[3]), "r"(b0), "r"(b1))

__device__ __forceinline__ uint32_t pack_bf2(__nv_bfloat16 lo, __nv_bfloat16 hi) {
    __nv_bfloat162 t(lo, hi);   // .x = lo half (low 16 bits)
    return *(uint32_t*)&t;
}

// ---------------- cluster-id decode ----------------
__global__ void prep_cid(const void* raw) {
    if (threadIdx.x == 0 && blockIdx.x == 0) {
        const int* r32 = (const int*)raw;
        bool is64 = true;
        for (int i = 0; i < 32; i++) {
            int lo = r32[2 * i], hi = r32[2 * i + 1];
            if (hi != 0 || lo < 0 || lo >= Cc) { is64 = false; break; }
        }
        if (is64) {
            const long long* r64 = (const long long*)raw;
            for (int i = 0; i < Nn; i++) g_cid[i] = (int)r64[i];
        } else {
            for (int i = 0; i < Nn; i++) g_cid[i] = r32[i];
        }
    }
}

// ---------------- fp32 -> (hi, lo) bf16 split ----------------
__global__ void conv_split4(const float4* __restrict__ src,
                            __nv_bfloat16* __restrict__ hi,
                            __nv_bfloat16* __restrict__ lo, int n4) {
    int i = blockIdx.x * blockDim.x + threadIdx.x;
    if (i >= n4) return;
    float4 v = src[i];
    __nv_bfloat16 h[4], l[4];
    float vv[4] = {v.x, v.y, v.z, v.w};
    #pragma unroll
    for (int j = 0; j < 4; j++) {
        h[j] = __float2bfloat16(vv[j]);
        l[j] = __float2bfloat16(vv[j] - __bfloat162float(h[j]));
    }
    *(uint2*)&hi[(size_t)i * 4] = *(uint2*)h;
    *(uint2*)&lo[(size_t)i * 4] = *(uint2*)l;
}

__global__ void conv_wkt(const float* __restrict__ Wk) {
    int idx = blockIdx.x * blockDim.x + threadIdx.x;
    if (idx >= Cc * Dd * Dd) return;
    int d = idx % Dd;
    int e = (idx / Dd) % Dd;
    int c = idx / (Dd * Dd);
    float v = Wk[((size_t)c * Dd + d) * Dd + e];
    __nv_bfloat16 h = __float2bfloat16(v);
    g_wkth[idx] = h;
    g_wktl[idx] = __float2bfloat16(v - __bfloat162float(h));
}

// ---------------- mma.sync split-bf16 GEMM ----------------
// CTA tile 128x256, warp tile 64x64 (8 warps), K chunks of 64, double-buffered.
// smem: A 2buf x (hi|lo) x 16KB = 64KB, then B 2buf x (hi|lo) x 32KB = 128KB.
#define A_PL 16384
#define B_PL 32768
#define A_BUF_STRIDE (2 * A_PL)          // 32768
#define B_BASE (4 * A_PL)                // 65536
#define B_BUF_STRIDE (2 * B_PL)          // 65536
#define GEMM_SMEM (B_BASE + 2 * B_BUF_STRIDE)   // 196608 (192 KB)

// SPLIT: write hi/lo bf16 planes (scaled); else fp32.
template<bool NODE, bool SPLIT>
__global__ __launch_bounds__(256, 1)
void gemm_mma(const __nv_bfloat16* __restrict__ Ah, const __nv_bfloat16* __restrict__ Al,
              long lda,
              const __nv_bfloat16* __restrict__ Wh, const __nv_bfloat16* __restrict__ Wl,
              const float* __restrict__ bias,
              float* __restrict__ Cf,
              __nv_bfloat16* __restrict__ Ch, __nv_bfloat16* __restrict__ Cl,
              float scale, long ldc)
{
    extern __shared__ char smem[];
    const uint32_t sb = smem_u32(smem);
    const int tid = threadIdx.x;
    const int wid = tid >> 5;
    const int lane = tid & 31;
    const int wm = wid >> 2;        // 0..1 -> 64-row slab
    const int wn = wid & 3;         // 0..3 -> 64-col slab

    size_t aoff = 0, woff = 0, boff = 0, coff = 0;
    if (NODE) {
        const int nn = blockIdx.z;
        const int cc = g_cid[nn];
        aoff = (size_t)nn * Dd;
        coff = aoff;
        woff = (size_t)cc * Dd * Dd;
        boff = (size_t)cc * Dd;
    }
    const int m0 = blockIdx.y * 128;
    const int n0 = blockIdx.x * 256;

    float acc[4][8][4];
    #pragma unroll
    for (int i = 0; i < 4; i++)
        #pragma unroll
        for (int j = 0; j < 8; j++)
            #pragma unroll
            for (int k = 0; k < 4; k++) acc[i][j][k] = 0.f;

    const int NC = Dd / 64;   // 8 chunks

    auto load_chunk = [&](int ci) {
        const int buf = ci & 1;
        const int koff = ci * 64;
        const uint32_t sA = sb + buf * A_BUF_STRIDE;
        const uint32_t sB = sb + B_BASE + buf * B_BUF_STRIDE;
        #pragma unroll
        for (int t = 0; t < 4; t++) {         // A: 128 rows x 8 granules
            const int idx = tid + t * 256;
            const int row = idx >> 3;
            const int c   = idx & 7;
            const uint32_t so = SWZ((uint32_t)(row * 128 + c * 16));
            const size_t ga = (size_t)(m0 + row) * lda + aoff + koff + c * 8;
            CP_ASYNC(sA + so,        &Ah[ga]);
            CP_ASYNC(sA + A_PL + so, &Al[ga]);
        }
        #pragma unroll
        for (int t = 0; t < 8; t++) {         // B: 256 rows x 8 granules
            const int idx = tid + t * 256;
            const int row = idx >> 3;
            const int c   = idx & 7;
            const uint32_t so = SWZ((uint32_t)(row * 128 + c * 16));
            const size_t gb = (size_t)(n0 + row) * Dd + woff + koff + c * 8;
            CP_ASYNC(sB + so,        &Wh[gb]);
            CP_ASYNC(sB + B_PL + so, &Wl[gb]);
        }
        CP_COMMIT();
    };

    load_chunk(0);

    const int ar = lane & 15, ag = lane >> 4;
    const int br = lane & 7,  bg = lane >> 3;

    for (int ci = 0; ci < NC; ci++) {
        if (ci + 1 < NC) { load_chunk(ci + 1); CP_WAIT(1); }
        else             { CP_WAIT(0); }
        __syncthreads();

        const int buf = ci & 1;
        const uint32_t sAh = sb + buf * A_BUF_STRIDE;
        const uint32_t sAl = sAh + A_PL;
        const uint32_t sBh = sb + B_BASE + buf * B_BUF_STRIDE;
        const uint32_t sBl = sBh + B_PL;

        #pragma unroll
        for (int p = 0; p < 3; p++) {
            const uint32_t sa  = (p == 2) ? sAl : sAh;    // hh, hl, lh
            const uint32_t sbp = (p == 1) ? sBl : sBh;
            #pragma unroll
            for (int ks = 0; ks < 4; ks++) {
                uint32_t afr[4][4];
                #pragma unroll
                for (int im = 0; im < 4; im++) {
                    const uint32_t off = SWZ((uint32_t)(
                        (wm * 64 + im * 16 + ar) * 128 + ks * 32 + ag * 16));
                    LDM_X4(afr[im], sa + off);
                }
                uint32_t bfr[4][4];
                #pragma unroll
                for (int ib = 0; ib < 4; ib++) {
                    const uint32_t off = SWZ((uint32_t)(
                        (wn * 64 + ib * 16 + (bg >> 1) * 8 + br) * 128 + ks * 32 + (bg & 1) * 16));
                    LDM_X4(bfr[ib], sbp + off);
                }
                #pragma unroll
                for (int im = 0; im < 4; im++) {
                    #pragma unroll
                    for (int in = 0; in < 8; in++) {
                        const uint32_t bb0 = bfr[in >> 1][(in & 1) * 2 + 0];
                        const uint32_t bb1 = bfr[in >> 1][(in & 1) * 2 + 1];
                        MMA16816(acc[im][in], afr[im], bb0, bb1);
                    }
                }
            }
        }
        __syncthreads();
    }

    // ---- epilogue ----
    const int rbase = m0 + wm * 64 + (lane >> 2);
    const int cbase = n0 + wn * 64 + (lane & 3) * 2;
    #pragma unroll
    for (int im = 0; im < 4; im++) {
        #pragma unroll
        for (int in = 0; in < 8; in++) {
            const int cg = cbase + in * 8;
            const float b0 = bias[boff + cg], b1 = bias[boff + cg + 1];
            const int r0 = rbase + im * 16;
            float v0 = acc[im][in][0] + b0, v1 = acc[im][in][1] + b1;
            float v2 = acc[im][in][2] + b0, v3 = acc[im][in][3] + b1;
            if (SPLIT) {
                v0 *= scale; v1 *= scale; v2 *= scale; v3 *= scale;
                __nv_bfloat16 h0 = __float2bfloat16(v0), h1 = __float2bfloat16(v1);
                __nv_bfloat16 h2 = __float2bfloat16(v2), h3 = __float2bfloat16(v3);
                __nv_bfloat16 l0 = __float2bfloat16(v0 - __bfloat162float(h0));
                __nv_bfloat16 l1 = __float2bfloat16(v1 - __bfloat162float(h1));
                __nv_bfloat16 l2 = __float2bfloat16(v2 - __bfloat162float(h2));
                __nv_bfloat16 l3 = __float2bfloat16(v3 - __bfloat162float(h3));
                *(uint32_t*)&Ch[(size_t)r0 * ldc + coff + cg]       = pack_bf2(h0, h1);
                *(uint32_t*)&Cl[(size_t)r0 * ldc + coff + cg]       = pack_bf2(l0, l1);
                *(uint32_t*)&Ch[(size_t)(r0 + 8) * ldc + coff + cg] = pack_bf2(h2, h3);
                *(uint32_t*)&Cl[(size_t)(r0 + 8) * ldc + coff + cg] = pack_bf2(l2, l3);
            } else {
                *(float2*)&Cf[(size_t)r0 * ldc + coff + cg]       = make_float2(v0, v1);
                *(float2*)&Cf[(size_t)(r0 + 8) * ldc + coff + cg] = make_float2(v2, v3);
            }
        }
    }
}

// ---------------- tensor-core flash attention ----------------
// One CTA per (b,n,h). 6 warps x 32 rows. S = Q*K^T (3-term split, Q pre-scaled),
// online softmax in fragments, out = P*V (3-term: ph*Vh + ph*Vl + pl*Vh).
#define PL 24576                          // one 192x64 bf16 plane, swizzled
#define ATTN_SMEM (6 * PL)                // 147456

__global__ __launch_bounds__(192, 1)
void attn_mma(const __nv_bfloat16* __restrict__ Qh_, const __nv_bfloat16* __restrict__ Ql_,
              const __nv_bfloat16* __restrict__ Kh_, const __nv_bfloat16* __restrict__ Kl_,
              const __nv_bfloat16* __restrict__ Vh_, const __nv_bfloat16* __restrict__ Vl_,
              __nv_bfloat16* __restrict__ Ah_, __nv_bfloat16* __restrict__ Al_)
{
    extern __shared__ char smem[];
    const uint32_t sb = smem_u32(smem);
    const int h = blockIdx.x, n = blockIdx.y, b = blockIdx.z;
    const int tid = threadIdx.x, wid = tid >> 5, lane = tid & 31;
    const size_t rowstride = (size_t)Nn * Dd;
    const size_t gbase = ((size_t)(b * Tt) * Nn + n) * Dd + (size_t)h * DH;

    // ---- load 6 planes into smem (swizzled 128B rows) ----
    {
        const __nv_bfloat16* srcs[6] = {Qh_ + gbase, Ql_ + gbase, Kh_ + gbase,
                                        Kl_ + gbase, Vh_ + gbase, Vl_ + gbase};
        #pragma unroll
        for (int p = 0; p < 6; p++) {
            const __nv_bfloat16* src = srcs[p];
            #pragma unroll
            for (int it = 0; it < 8; it++) {
                const int idx = tid + it * 192;     // 0..1535
                const int row = idx >> 3, g = idx & 7;
                *(uint4*)(smem + p * PL + SWZ(row * 128 + g * 16)) =
                    *(const uint4*)&src[(size_t)row * rowstride + g * 8];
            }
        }
    }
    __syncthreads();

    const int mbase = wid * 32;
    float mrow[4] = {-1e30f, -1e30f, -1e30f, -1e30f};   // slot = mt*2 + (elpair)
    float lrow[4] = {0.f, 0.f, 0.f, 0.f};
    float ofr[2][8][4];
    #pragma unroll
    for (int a = 0; a < 2; a++)
        #pragma unroll
        for (int c = 0; c < 8; c++)
            #pragma unroll
            for (int e = 0; e < 4; e++) ofr[a][c][e] = 0.f;

    const int ar = lane & 15, ag = lane >> 4;
    const int br = lane & 7,  bg = lane >> 3;

    for (int sb3 = 0; sb3 < 3; sb3++) {
        // ---- S = Q K^T over 64 s-cols (8 n-tiles), 3 passes ----
        float sfr[2][8][4];
        #pragma unroll
        for (int a = 0; a < 2; a++)
            #pragma unroll
            for (int c = 0; c < 8; c++)
                #pragma unroll
                for (int e = 0; e < 4; e++) sfr[a][c][e] = 0.f;

        #pragma unroll
        for (int p = 0; p < 3; p++) {
            const uint32_t qs = sb + ((p < 2) ? 0 : 1) * PL;
            const uint32_t ks_ = sb + ((p == 1) ? 3 : 2) * PL;
            #pragma unroll
            for (int ks = 0; ks < 4; ks++) {
                uint32_t afr[2][4];
                #pragma unroll
                for (int mt = 0; mt < 2; mt++)
                    LDM_X4(afr[mt], qs + SWZ((uint32_t)(
                        (mbase + mt * 16 + ar) * 128 + ks * 32 + ag * 16)));
                #pragma unroll
                for (int ib = 0; ib < 4; ib++) {
                    uint32_t bfr[4];
                    LDM_X4(bfr, ks_ + SWZ((uint32_t)(
                        (sb3 * 64 + ib * 16 + (bg >> 1) * 8 + br) * 128 + ks * 32 + (bg & 1) * 16)));
                    #pragma unroll
                    for (int mt = 0; mt < 2; mt++) {
                        MMA16816(sfr[mt][2 * ib],     afr[mt], bfr[0], bfr[1]);
                        MMA16816(sfr[mt][2 * ib + 1], afr[mt], bfr[2], bfr[3]);
                    }
                }
            }
        }

        // ---- online softmax ----
        float alpha[4];
        #pragma unroll
        for (int sl = 0; sl < 4; sl++) {
            const int mt = sl >> 1, rr = sl & 1;
            float mx = -1e30f;
            #pragma unroll
            for (int nt = 0; nt < 8; nt++)
                mx = fmaxf(mx, fmaxf(sfr[mt][nt][rr * 2], sfr[mt][nt][rr * 2 + 1]));
            mx = fmaxf(mx, __shfl_xor_sync(0xFFFFFFFFu, mx, 1));
            mx = fmaxf(mx, __shfl_xor_sync(0xFFFFFFFFu, mx, 2));
            const float mn = fmaxf(mrow[sl], mx);
            alpha[sl] = __expf(mrow[sl] - mn);
            mrow[sl] = mn;
            lrow[sl] *= alpha[sl];
        }
        #pragma unroll
        for (int mt = 0; mt < 2; mt++)
            #pragma unroll
            for (int nt = 0; nt < 8; nt++) {
                ofr[mt][nt][0] *= alpha[mt * 2];     ofr[mt][nt][1] *= alpha[mt * 2];
                ofr[mt][nt][2] *= alpha[mt * 2 + 1]; ofr[mt][nt][3] *= alpha[mt * 2 + 1];
            }

        // P = exp(S - m), split to (ph, pl) packed as A-fragment halves
        uint32_t ph[2][8][2], pl[2][8][2];
        #pragma unroll
        for (int mt = 0; mt < 2; mt++) {
            #pragma unroll
            for (int nt = 0; nt < 8; nt++) {
                const float p0 = __expf(sfr[mt][nt][0] - mrow[mt * 2]);
                const float p1 = __expf(sfr[mt][nt][1] - mrow[mt * 2]);
                const float p2 = __expf(sfr[mt][nt][2] - mrow[mt * 2 + 1]);
                const float p3 = __expf(sfr[mt][nt][3] - mrow[mt * 2 + 1]);
                lrow[mt * 2]     += p0 + p1;
                lrow[mt * 2 + 1] += p2 + p3;
                const __nv_bfloat16 h0 = __float2bfloat16(p0), h1 = __float2bfloat16(p1);
                const __nv_bfloat16 h2 = __float2bfloat16(p2), h3 = __float2bfloat16(p3);
                ph[mt][nt][0] = pack_bf2(h0, h1);
                ph[mt][nt][1] = pack_bf2(h2, h3);
                pl[mt][nt][0] = pack_bf2(__float2bfloat16(p0 - __bfloat162float(h0)),
                                         __float2bfloat16(p1 - __bfloat162float(h1)));
                pl[mt][nt][1] = pack_bf2(__float2bfloat16(p2 - __bfloat162float(h2)),
                                         __float2bfloat16(p3 - __bfloat162float(h3)));
            }
        }

        // ---- out += P * V : passes (ph,Vh), (ph,Vl), (pl,Vh) ----
        const int g = lane >> 3;
        #pragma unroll
        for (int q = 0; q < 3; q++) {
            const uint32_t vs = sb + ((q == 1) ? 5 : 4) * PL;
            #pragma unroll
            for (int ks2 = 0; ks2 < 4; ks2++) {
                #pragma unroll
                for (int j = 0; j < 4; j++) {
                    uint32_t vfr[4];
                    const int srow = sb3 * 64 + ks2 * 16 + (g & 1) * 8 + (lane & 7);
                    const int gran = 2 * j + (g >> 1);
                    LDM_X4T(vfr, vs + SWZ((uint32_t)(srow * 128 + gran * 16)));
                    #pragma unroll
                    for (int mt = 0; mt < 2; mt++) {
                        uint32_t af[4];
                        if (q == 2) {
                            af[0] = pl[mt][2 * ks2][0];     af[1] = pl[mt][2 * ks2][1];
                            af[2] = pl[mt][2 * ks2 + 1][0]; af[3] = pl[mt][2 * ks2 + 1][1];
                        } else {
                            af[0] = ph[mt][2 * ks2][0];     af[1] = ph[mt][2 * ks2][1];
                            af[2] = ph[mt][2 * ks2 + 1][0]; af[3] = ph[mt][2 * ks2 + 1][1];
                        }
                        MMA16816(ofr[mt][2 * j],     af, vfr[0], vfr[1]);
                        MMA16816(ofr[mt][2 * j + 1], af, vfr[2], vfr[3]);
                    }
                }
            }
        }
    }

    // ---- finalize: normalize and write split output ----
    float inv[4];
    #pragma unroll
    for (int sl = 0; sl < 4; sl++) {
        float l = lrow[sl];
        l += __shfl_xor_sync(0xFFFFFFFFu, l, 1);
        l += __shfl_xor_sync(0xFFFFFFFFu, l, 2);
        inv[sl] = 1.f / l;
    }
    #pragma unroll
    for (int mt = 0; mt < 2; mt++) {
        #pragma unroll
        for (int rr = 0; rr < 2; rr++) {
            const int t = mbase + mt * 16 + (lane >> 2) + rr * 8;
            const float iv = inv[mt * 2 + rr];
            #pragma unroll
            for (int nt = 0; nt < 8; nt++) {
                const int dh = nt * 8 + (lane & 3) * 2;
                const float v0 = ofr[mt][nt][rr * 2] * iv;
                const float v1 = ofr[mt][nt][rr * 2 + 1] * iv;
                const __nv_bfloat16 h0 = __float2bfloat16(v0), h1 = __float2bfloat16(v1);
                const size_t gidx = gbase + (size_t)t * rowstride + dh;
                *(uint32_t*)&Ah_[gidx] = pack_bf2(h0, h1);
                *(uint32_t*)&Al_[gidx] = pack_bf2(__float2bfloat16(v0 - __bfloat162float(h0)),
                                                  __float2bfloat16(v1 - __bfloat162float(h1)));
            }
        }
    }
}

// ---------------- launcher ----------------
extern "C" void kernel_launch(void* const* d_in, const int* in_sizes, int n_in,
                              void* d_out, int out_size)
{
    const float* x      = (const float*)d_in[0];
    const float* Wq_w   = (const float*)d_in[1];
    const float* Wq_b   = (const float*)d_in[2];
    const float* Wv_w   = (const float*)d_in[3];
    const float* Wv_b   = (const float*)d_in[4];
    const float* Wk     = (const float*)d_in[5];
    const float* bk     = (const float*)d_in[6];
    const float* proj_w = (const float*)d_in[7];
    const float* proj_b = (const float*)d_in[8];
    const void*  cid    = d_in[9];
    float* out = (float*)d_out;

    void *pQh, *pQl, *pKh, *pKl, *pVh, *pVl, *pxh, *pxl, *pAh, *pAl;
    void *pwqh, *pwql, *pwvh, *pwvl, *pwph, *pwpl, *pwkth, *pwktl;
    cudaGetSymbolAddress(&pQh, g_Qh);  cudaGetSymbolAddress(&pQl, g_Ql);
    cudaGetSymbolAddress(&pKh, g_Kh);  cudaGetSymbolAddress(&pKl, g_Kl);
    cudaGetSymbolAddress(&pVh, g_Vh);  cudaGetSymbolAddress(&pVl, g_Vl);
    cudaGetSymbolAddress(&pxh, g_xh);  cudaGetSymbolAddress(&pxl, g_xl);
    cudaGetSymbolAddress(&pAh, g_Ah);  cudaGetSymbolAddress(&pAl, g_Al);
    cudaGetSymbolAddress(&pwqh, g_wqh); cudaGetSymbolAddress(&pwql, g_wql);
    cudaGetSymbolAddress(&pwvh, g_wvh); cudaGetSymbolAddress(&pwvl, g_wvl);
    cudaGetSymbolAddress(&pwph, g_wph); cudaGetSymbolAddress(&pwpl, g_wpl);
    cudaGetSymbolAddress(&pwkth, g_wkth); cudaGetSymbolAddress(&pwktl, g_wktl);

    cudaFuncSetAttribute(gemm_mma<false, true>,  cudaFuncAttributeMaxDynamicSharedMemorySize, GEMM_SMEM);
    cudaFuncSetAttribute(gemm_mma<true,  true>,  cudaFuncAttributeMaxDynamicSharedMemorySize, GEMM_SMEM);
    cudaFuncSetAttribute(gemm_mma<false, false>, cudaFuncAttributeMaxDynamicSharedMemorySize, GEMM_SMEM);
    cudaFuncSetAttribute(attn_mma, cudaFuncAttributeMaxDynamicSharedMemorySize, ATTN_SMEM);

    prep_cid<<<1, 32>>>(cid);

    const int n4x = (M_ALL * Dd) / 4;
    conv_split4<<<(n4x + 255) / 256, 256>>>((const float4*)x,
                                            (__nv_bfloat16*)pxh, (__nv_bfloat16*)pxl, n4x);
    const int n4w = (Dd * Dd) / 4;
    conv_split4<<<(n4w + 255) / 256, 256>>>((const float4*)Wq_w,
                                            (__nv_bfloat16*)pwqh, (__nv_bfloat16*)pwql, n4w);
    conv_split4<<<(n4w + 255) / 256, 256>>>((const float4*)Wv_w,
                                            (__nv_bfloat16*)pwvh, (__nv_bfloat16*)pwvl, n4w);
    conv_split4<<<(n4w + 255) / 256, 256>>>((const float4*)proj_w,
                                            (__nv_bfloat16*)pwph, (__nv_bfloat16*)pwpl, n4w);
    conv_wkt<<<(Cc * Dd * Dd + 255) / 256, 256>>>(Wk);

    dim3 gfull(Dd / 256, M_ALL / 128, 1);   // (2, 768)
    dim3 gnode(Dd / 256, BT / 128, Nn);     // (2, 12, 64)

    // Q: pre-scaled by 1/sqrt(DH) = 0.125 (exact power of two)
    gemm_mma<false, true><<<gfull, 256, GEMM_SMEM>>>(
        (const __nv_bfloat16*)pxh, (const __nv_bfloat16*)pxl, Dd,
        (const __nv_bfloat16*)pwqh, (const __nv_bfloat16*)pwql, Wq_b,
        nullptr, (__nv_bfloat16*)pQh, (__nv_bfloat16*)pQl, 0.125f, Dd);
    gemm_mma<false, true><<<gfull, 256, GEMM_SMEM>>>(
        (const __nv_bfloat16*)pxh, (const __nv_bfloat16*)pxl, Dd,
        (const __nv_bfloat16*)pwvh, (const __nv_bfloat16*)pwvl, Wv_b,
        nullptr, (__nv_bfloat16*)pVh, (__nv_bfloat16*)pVl, 1.0f, Dd);
    gemm_mma<true, true><<<gnode, 256, GEMM_SMEM>>>(
        (const __nv_bfloat16*)pxh, (const __nv_bfloat16*)pxl, (long)Nn * Dd,
        (const __nv_bfloat16*)pwkth, (const __nv_bfloat16*)pwktl, bk,
        nullptr, (__nv_bfloat16*)pKh, (__nv_bfloat16*)pKl, 1.0f, (long)Nn * Dd);

    dim3 gattn(Hh, Nn, Bb);
    attn_mma<<<gattn, 192, ATTN_SMEM>>>(
        (const __nv_bfloat16*)pQh, (const __nv_bfloat16*)pQl,
        (const __nv_bfloat16*)pKh, (const __nv_bfloat16*)pKl,
        (const __nv_bfloat16*)pVh, (const __nv_bfloat16*)pVl,
        (__nv_bfloat16*)pAh, (__nv_bfloat16*)pAl);

    gemm_mma<false, false><<<gfull, 256, GEMM_SMEM>>>(
        (const __nv_bfloat16*)pAh, (const __nv_bfloat16*)pAl, Dd,
        (const __nv_bfloat16*)pwph, (const __nv_bfloat16*)pwpl, proj_b,
        out, nullptr, nullptr, 1.0f, Dd);
}

// round 11
// speedup vs baseline: 1.1137x; 1.1137x over previous
#include <cuda_runtime.h>
#include <cuda_bf16.h>
#include <cstdint>

// ---------------- problem constants ----------------
#define Bb   8
#define Tt   192
#define Nn   64
#define Dd   512
#define Hh   8
#define DH   64
#define Cc   8
#define BT   (Bb * Tt)            // 1536
#define M_ALL (Bb * Tt * Nn)      // 98304

#define SWZ(o) ((o) ^ (((o) >> 3) & 0x70))

// ---------------- scratch ----------------
__device__ __nv_bfloat16 g_Qh[(size_t)M_ALL * Dd], g_Ql[(size_t)M_ALL * Dd];
__device__ __nv_bfloat16 g_Kh[(size_t)M_ALL * Dd], g_Kl[(size_t)M_ALL * Dd];
__device__ __nv_bfloat16 g_Vh[(size_t)M_ALL * Dd], g_Vl[(size_t)M_ALL * Dd];
__device__ __nv_bfloat16 g_xh[(size_t)M_ALL * Dd], g_xl[(size_t)M_ALL * Dd];
__device__ __nv_bfloat16 g_Ah[(size_t)M_ALL * Dd], g_Al[(size_t)M_ALL * Dd];
__device__ __nv_bfloat16 g_wqh[Dd * Dd], g_wql[Dd * Dd];
__device__ __nv_bfloat16 g_wvh[Dd * Dd], g_wvl[Dd * Dd];
__device__ __nv_bfloat16 g_wph[Dd * Dd], g_wpl[Dd * Dd];
__device__ __nv_bfloat16 g_wkth[(size_t)Cc * Dd * Dd], g_wktl[(size_t)Cc * Dd * Dd];
__device__ int g_cid[Nn];

// ---------------- PTX helpers (portable) ----------------
__device__ __forceinline__ uint32_t smem_u32(const void* p) {
    uint32_t a;
    asm("{ .reg .u64 t; cvta.to.shared.u64 t, %1; cvt.u32.u64 %0, t; }" : "=r"(a) : "l"(p));
    return a;
}
#define CP_ASYNC(dst, src) \
    asm volatile("cp.async.cg.shared.global [%0], [%1], 16;" :: "r"(dst), "l"(src))
#define CP_COMMIT() asm volatile("cp.async.commit_group;" ::: "memory")
#define CP_WAIT(n)  asm volatile("cp.async.wait_group %0;" :: "n"(n) : "memory")

#define LDM_X4(r, addr) \
    asm volatile("ldmatrix.sync.aligned.m8n8.x4.shared.b16 {%0,%1,%2,%3}, [%4];" \
        : "=r"((r)[0]), "=r"((r)[1]), "=r"((r)[2]), "=r"((r)[3]) : "r"(addr))

#define LDM_X4T(r, addr) \
    asm volatile("ldmatrix.sync.aligned.m8n8.x4.trans.shared.b16 {%0,%1,%2,%3}, [%4];" \
        : "=r"((r)[0]), "=r"((r)[1]), "=r"((r)[2]), "=r"((r)[3]) : "r"(addr))

#define MMA16816(d, a, b0, b1) \
    asm volatile("mma.sync.aligned.m16n8k16.row.col.f32.bf16.bf16.f32 " \
        "{%0,%1,%2,%3}, {%4,%5,%6,%7}, {%8,%9}, {%0,%1,%2,%3};" \
        : "+f"((d)[0]), "+f"((d)[1]), "+f"((d)[2]), "+f"((d)[3]) \
        : "r"((a)[0]), "r"((a)[1]), "r"((a)[2]), "r"((a)[3]), "r"(b0), "r"(b1))

__device__ __forceinline__ uint32_t pack_bf2(__nv_bfloat16 lo, __nv_bfloat16 hi) {
    __nv_bfloat162 t(lo, hi);   // .x = lo half (low 16 bits)
    return *(uint32_t*)&t;
}

// ---------------- cluster-id decode ----------------
__global__ void prep_cid(const void* raw) {
    if (threadIdx.x == 0 && blockIdx.x == 0) {
        const int* r32 = (const int*)raw;
        bool is64 = true;
        for (int i = 0; i < 32; i++) {
            int lo = r32[2 * i], hi = r32[2 * i + 1];
            if (hi != 0 || lo < 0 || lo >= Cc) { is64 = false; break; }
        }
        if (is64) {
            const long long* r64 = (const long long*)raw;
            for (int i = 0; i < Nn; i++) g_cid[i] = (int)r64[i];
        } else {
            for (int i = 0; i < Nn; i++) g_cid[i] = r32[i];
        }
    }
}

// ---------------- fp32 -> (hi, lo) bf16 split ----------------
__global__ void conv_split4(const float4* __restrict__ src,
                            __nv_bfloat16* __restrict__ hi,
                            __nv_bfloat16* __restrict__ lo, int n4) {
    int i = blockIdx.x * blockDim.x + threadIdx.x;
    if (i >= n4) return;
    float4 v = src[i];
    __nv_bfloat16 h[4], l[4];
    float vv[4] = {v.x, v.y, v.z, v.w};
    #pragma unroll
    for (int j = 0; j < 4; j++) {
        h[j] = __float2bfloat16(vv[j]);
        l[j] = __float2bfloat16(vv[j] - __bfloat162float(h[j]));
    }
    *(uint2*)&hi[(size_t)i * 4] = *(uint2*)h;
    *(uint2*)&lo[(size_t)i * 4] = *(uint2*)l;
}

__global__ void conv_wkt(const float* __restrict__ Wk) {
    int idx = blockIdx.x * blockDim.x + threadIdx.x;
    if (idx >= Cc * Dd * Dd) return;
    int d = idx % Dd;
    int e = (idx / Dd) % Dd;
    int c = idx / (Dd * Dd);
    float v = Wk[((size_t)c * Dd + d) * Dd + e];
    __nv_bfloat16 h = __float2bfloat16(v);
    g_wkth[idx] = h;
    g_wktl[idx] = __float2bfloat16(v - __bfloat162float(h));
}

// ---------------- mma.sync split-bf16 GEMM ----------------
// CTA tile 128x128, warp tile 64x32 (8 warps), K chunks of 64, double-buffered.
// Hoisted fragments: per k16-step load A-hi/A-lo/B-hi/B-lo once (12 LDSM),
// then issue all 48 MMAs of the 3 split passes (hh, hl, lh).
#define CHUNK_B 16384
#define BUF_STRIDE (2 * CHUNK_B)
#define B_OFF (4 * CHUNK_B)
#define GEMM_SMEM (8 * CHUNK_B)          // 131072

// SPLIT: write hi/lo bf16 planes (scaled); else fp32.
template<bool NODE, bool SPLIT>
__global__ __launch_bounds__(256, 1)
void gemm_mma(const __nv_bfloat16* __restrict__ Ah, const __nv_bfloat16* __restrict__ Al,
              long lda,
              const __nv_bfloat16* __restrict__ Wh, const __nv_bfloat16* __restrict__ Wl,
              const float* __restrict__ bias,
              float* __restrict__ Cf,
              __nv_bfloat16* __restrict__ Ch, __nv_bfloat16* __restrict__ Cl,
              float scale, long ldc)
{
    extern __shared__ char smem[];
    const uint32_t sb = smem_u32(smem);
    const int tid = threadIdx.x;
    const int wid = tid >> 5;
    const int lane = tid & 31;
    const int wm = wid >> 2;        // 0..1 -> 64-row slab
    const int wn = wid & 3;         // 0..3 -> 32-col slab

    size_t aoff = 0, woff = 0, boff = 0, coff = 0;
    if (NODE) {
        const int nn = blockIdx.z;
        const int cc = g_cid[nn];
        aoff = (size_t)nn * Dd;
        coff = aoff;
        woff = (size_t)cc * Dd * Dd;
        boff = (size_t)cc * Dd;
    }
    const int m0 = blockIdx.y * 128;
    const int n0 = blockIdx.x * 128;

    float acc[4][4][4];
    #pragma unroll
    for (int i = 0; i < 4; i++)
        #pragma unroll
        for (int j = 0; j < 4; j++)
            #pragma unroll
            for (int k = 0; k < 4; k++) acc[i][j][k] = 0.f;

    const int NC = Dd / 64;

    auto load_chunk = [&](int ci) {
        const int buf = ci & 1;
        const int koff = ci * 64;
        const uint32_t sA = sb + buf * BUF_STRIDE;
        const uint32_t sB = sb + B_OFF + buf * BUF_STRIDE;
        #pragma unroll
        for (int t = 0; t < 4; t++) {
            const int idx = tid + t * 256;
            const int row = idx >> 3;
            const int c   = idx & 7;
            const uint32_t so = SWZ((uint32_t)(row * 128 + c * 16));
            const size_t ga = (size_t)(m0 + row) * lda + aoff + koff + c * 8;
            CP_ASYNC(sA + so,           &Ah[ga]);
            CP_ASYNC(sA + CHUNK_B + so, &Al[ga]);
            const size_t gb = (size_t)(n0 + row) * Dd + woff + koff + c * 8;
            CP_ASYNC(sB + so,           &Wh[gb]);
            CP_ASYNC(sB + CHUNK_B + so, &Wl[gb]);
        }
        CP_COMMIT();
    };

    load_chunk(0);

    const int ar = lane & 15, ag = lane >> 4;
    const int br = lane & 7,  bg = lane >> 3;

    for (int ci = 0; ci < NC; ci++) {
        if (ci + 1 < NC) { load_chunk(ci + 1); CP_WAIT(1); }
        else             { CP_WAIT(0); }
        __syncthreads();

        const int buf = ci & 1;
        const uint32_t sAh = sb + buf * BUF_STRIDE;
        const uint32_t sAl = sAh + CHUNK_B;
        const uint32_t sBh = sb + B_OFF + buf * BUF_STRIDE;
        const uint32_t sBl = sBh + CHUNK_B;

        #pragma unroll
        for (int ks = 0; ks < 4; ks++) {
            // ---- hoisted fragment loads: 12 LDSM.x4 feed 48 MMAs ----
            uint32_t ah[4][4], al[4][4];
            #pragma unroll
            for (int im = 0; im < 4; im++) {
                const uint32_t off = SWZ((uint32_t)(
                    (wm * 64 + im * 16 + ar) * 128 + ks * 32 + ag * 16));
                LDM_X4(ah[im], sAh + off);
                LDM_X4(al[im], sAl + off);
            }
            uint32_t bh[2][4], bl[2][4];
            #pragma unroll
            for (int ib = 0; ib < 2; ib++) {
                const uint32_t off = SWZ((uint32_t)(
                    (wn * 32 + ib * 16 + (bg >> 1) * 8 + br) * 128 + ks * 32 + (bg & 1) * 16));
                LDM_X4(bh[ib], sBh + off);
                LDM_X4(bl[ib], sBl + off);
            }
            // ---- pass hh ----
            #pragma unroll
            for (int im = 0; im < 4; im++)
                #pragma unroll
                for (int in = 0; in < 4; in++)
                    MMA16816(acc[im][in], ah[im],
                             bh[in >> 1][(in & 1) * 2 + 0], bh[in >> 1][(in & 1) * 2 + 1]);
            // ---- pass hl ----
            #pragma unroll
            for (int im = 0; im < 4; im++)
                #pragma unroll
                for (int in = 0; in < 4; in++)
                    MMA16816(acc[im][in], ah[im],
                             bl[in >> 1][(in & 1) * 2 + 0], bl[in >> 1][(in & 1) * 2 + 1]);
            // ---- pass lh ----
            #pragma unroll
            for (int im = 0; im < 4; im++)
                #pragma unroll
                for (int in = 0; in < 4; in++)
                    MMA16816(acc[im][in], al[im],
                             bh[in >> 1][(in & 1) * 2 + 0], bh[in >> 1][(in & 1) * 2 + 1]);
        }
        __syncthreads();
    }

    // ---- epilogue ----
    const int rbase = m0 + wm * 64 + (lane >> 2);
    const int cbase = n0 + wn * 32 + (lane & 3) * 2;
    #pragma unroll
    for (int im = 0; im < 4; im++) {
        #pragma unroll
        for (int in = 0; in < 4; in++) {
            const int cg = cbase + in * 8;
            const float b0 = bias[boff + cg], b1 = bias[boff + cg + 1];
            const int r0 = rbase + im * 16;
            float v0 = acc[im][in][0] + b0, v1 = acc[im][in][1] + b1;
            float v2 = acc[im][in][2] + b0, v3 = acc[im][in][3] + b1;
            if (SPLIT) {
                v0 *= scale; v1 *= scale; v2 *= scale; v3 *= scale;
                __nv_bfloat16 h0 = __float2bfloat16(v0), h1 = __float2bfloat16(v1);
                __nv_bfloat16 h2 = __float2bfloat16(v2), h3 = __float2bfloat16(v3);
                __nv_bfloat16 l0 = __float2bfloat16(v0 - __bfloat162float(h0));
                __nv_bfloat16 l1 = __float2bfloat16(v1 - __bfloat162float(h1));
                __nv_bfloat16 l2 = __float2bfloat16(v2 - __bfloat162float(h2));
                __nv_bfloat16 l3 = __float2bfloat16(v3 - __bfloat162float(h3));
                *(uint32_t*)&Ch[(size_t)r0 * ldc + coff + cg]       = pack_bf2(h0, h1);
                *(uint32_t*)&Cl[(size_t)r0 * ldc + coff + cg]       = pack_bf2(l0, l1);
                *(uint32_t*)&Ch[(size_t)(r0 + 8) * ldc + coff + cg] = pack_bf2(h2, h3);
                *(uint32_t*)&Cl[(size_t)(r0 + 8) * ldc + coff + cg] = pack_bf2(l2, l3);
            } else {
                *(float2*)&Cf[(size_t)r0 * ldc + coff + cg]       = make_float2(v0, v1);
                *(float2*)&Cf[(size_t)(r0 + 8) * ldc + coff + cg] = make_float2(v2, v3);
            }
        }
    }
}

// ---------------- tensor-core flash attention ----------------
// One CTA per (b,n,h). 6 warps x 32 rows. S = Q*K^T (3-term split, Q pre-scaled),
// online softmax in fragments, out = P*V (3-term: ph*Vh + ph*Vl + pl*Vh).
#define PL 24576                          // one 192x64 bf16 plane, swizzled
#define ATTN_SMEM (6 * PL)                // 147456

__global__ __launch_bounds__(192, 1)
void attn_mma(const __nv_bfloat16* __restrict__ Qh_, const __nv_bfloat16* __restrict__ Ql_,
              const __nv_bfloat16* __restrict__ Kh_, const __nv_bfloat16* __restrict__ Kl_,
              const __nv_bfloat16* __restrict__ Vh_, const __nv_bfloat16* __restrict__ Vl_,
              __nv_bfloat16* __restrict__ Ah_, __nv_bfloat16* __restrict__ Al_)
{
    extern __shared__ char smem[];
    const uint32_t sb = smem_u32(smem);
    const int h = blockIdx.x, n = blockIdx.y, b = blockIdx.z;
    const int tid = threadIdx.x, wid = tid >> 5, lane = tid & 31;
    const size_t rowstride = (size_t)Nn * Dd;
    const size_t gbase = ((size_t)(b * Tt) * Nn + n) * Dd + (size_t)h * DH;

    // ---- load 6 planes into smem (swizzled 128B rows) ----
    {
        const __nv_bfloat16* srcs[6] = {Qh_ + gbase, Ql_ + gbase, Kh_ + gbase,
                                        Kl_ + gbase, Vh_ + gbase, Vl_ + gbase};
        #pragma unroll
        for (int p = 0; p < 6; p++) {
            const __nv_bfloat16* src = srcs[p];
            #pragma unroll
            for (int it = 0; it < 8; it++) {
                const int idx = tid + it * 192;     // 0..1535
                const int row = idx >> 3, g = idx & 7;
                *(uint4*)(smem + p * PL + SWZ(row * 128 + g * 16)) =
                    *(const uint4*)&src[(size_t)row * rowstride + g * 8];
            }
        }
    }
    __syncthreads();

    const int mbase = wid * 32;
    float mrow[4] = {-1e30f, -1e30f, -1e30f, -1e30f};   // slot = mt*2 + (elpair)
    float lrow[4] = {0.f, 0.f, 0.f, 0.f};
    float ofr[2][8][4];
    #pragma unroll
    for (int a = 0; a < 2; a++)
        #pragma unroll
        for (int c = 0; c < 8; c++)
            #pragma unroll
            for (int e = 0; e < 4; e++) ofr[a][c][e] = 0.f;

    const int ar = lane & 15, ag = lane >> 4;
    const int br = lane & 7,  bg = lane >> 3;

    for (int sb3 = 0; sb3 < 3; sb3++) {
        // ---- S = Q K^T over 64 s-cols (8 n-tiles), 3 passes ----
        float sfr[2][8][4];
        #pragma unroll
        for (int a = 0; a < 2; a++)
            #pragma unroll
            for (int c = 0; c < 8; c++)
                #pragma unroll
                for (int e = 0; e < 4; e++) sfr[a][c][e] = 0.f;

        #pragma unroll
        for (int p = 0; p < 3; p++) {
            const uint32_t qs = sb + ((p < 2) ? 0 : 1) * PL;
            const uint32_t ks_ = sb + ((p == 1) ? 3 : 2) * PL;
            #pragma unroll
            for (int ks = 0; ks < 4; ks++) {
                uint32_t afr[2][4];
                #pragma unroll
                for (int mt = 0; mt < 2; mt++)
                    LDM_X4(afr[mt], qs + SWZ((uint32_t)(
                        (mbase + mt * 16 + ar) * 128 + ks * 32 + ag * 16)));
                #pragma unroll
                for (int ib = 0; ib < 4; ib++) {
                    uint32_t bfr[4];
                    LDM_X4(bfr, ks_ + SWZ((uint32_t)(
                        (sb3 * 64 + ib * 16 + (bg >> 1) * 8 + br) * 128 + ks * 32 + (bg & 1) * 16)));
                    #pragma unroll
                    for (int mt = 0; mt < 2; mt++) {
                        MMA16816(sfr[mt][2 * ib],     afr[mt], bfr[0], bfr[1]);
                        MMA16816(sfr[mt][2 * ib + 1], afr[mt], bfr[2], bfr[3]);
                    }
                }
            }
        }

        // ---- online softmax ----
        float alpha[4];
        #pragma unroll
        for (int sl = 0; sl < 4; sl++) {
            const int mt = sl >> 1, rr = sl & 1;
            float mx = -1e30f;
            #pragma unroll
            for (int nt = 0; nt < 8; nt++)
                mx = fmaxf(mx, fmaxf(sfr[mt][nt][rr * 2], sfr[mt][nt][rr * 2 + 1]));
            mx = fmaxf(mx, __shfl_xor_sync(0xFFFFFFFFu, mx, 1));
            mx = fmaxf(mx, __shfl_xor_sync(0xFFFFFFFFu, mx, 2));
            const float mn = fmaxf(mrow[sl], mx);
            alpha[sl] = __expf(mrow[sl] - mn);
            mrow[sl] = mn;
            lrow[sl] *= alpha[sl];
        }
        #pragma unroll
        for (int mt = 0; mt < 2; mt++)
            #pragma unroll
            for (int nt = 0; nt < 8; nt++) {
                ofr[mt][nt][0] *= alpha[mt * 2];     ofr[mt][nt][1] *= alpha[mt * 2];
                ofr[mt][nt][2] *= alpha[mt * 2 + 1]; ofr[mt][nt][3] *= alpha[mt * 2 + 1];
            }

        // P = exp(S - m), split to (ph, pl) packed as A-fragment halves
        uint32_t ph[2][8][2], pl[2][8][2];
        #pragma unroll
        for (int mt = 0; mt < 2; mt++) {
            #pragma unroll
            for (int nt = 0; nt < 8; nt++) {
                const float p0 = __expf(sfr[mt][nt][0] - mrow[mt * 2]);
                const float p1 = __expf(sfr[mt][nt][1] - mrow[mt * 2]);
                const float p2 = __expf(sfr[mt][nt][2] - mrow[mt * 2 + 1]);
                const float p3 = __expf(sfr[mt][nt][3] - mrow[mt * 2 + 1]);
                lrow[mt * 2]     += p0 + p1;
                lrow[mt * 2 + 1] += p2 + p3;
                const __nv_bfloat16 h0 = __float2bfloat16(p0), h1 = __float2bfloat16(p1);
                const __nv_bfloat16 h2 = __float2bfloat16(p2), h3 = __float2bfloat16(p3);
                ph[mt][nt][0] = pack_bf2(h0, h1);
                ph[mt][nt][1] = pack_bf2(h2, h3);
                pl[mt][nt][0] = pack_bf2(__float2bfloat16(p0 - __bfloat162float(h0)),
                                         __float2bfloat16(p1 - __bfloat162float(h1)));
                pl[mt][nt][1] = pack_bf2(__float2bfloat16(p2 - __bfloat162float(h2)),
                                         __float2bfloat16(p3 - __bfloat162float(h3)));
            }
        }

        // ---- out += P * V : passes (ph,Vh), (ph,Vl), (pl,Vh) ----
        const int g = lane >> 3;
        #pragma unroll
        for (int q = 0; q < 3; q++) {
            const uint32_t vs = sb + ((q == 1) ? 5 : 4) * PL;
            #pragma unroll
            for (int ks2 = 0; ks2 < 4; ks2++) {
                #pragma unroll
                for (int j = 0; j < 4; j++) {
                    uint32_t vfr[4];
                    const int srow = sb3 * 64 + ks2 * 16 + (g & 1) * 8 + (lane & 7);
                    const int gran = 2 * j + (g >> 1);
                    LDM_X4T(vfr, vs + SWZ((uint32_t)(srow * 128 + gran * 16)));
                    #pragma unroll
                    for (int mt = 0; mt < 2; mt++) {
                        uint32_t af[4];
                        if (q == 2) {
                            af[0] = pl[mt][2 * ks2][0];     af[1] = pl[mt][2 * ks2][1];
                            af[2] = pl[mt][2 * ks2 + 1][0]; af[3] = pl[mt][2 * ks2 + 1][1];
                        } else {
                            af[0] = ph[mt][2 * ks2][0];     af[1] = ph[mt][2 * ks2][1];
                            af[2] = ph[mt][2 * ks2 + 1][0]; af[3] = ph[mt][2 * ks2 + 1][1];
                        }
                        MMA16816(ofr[mt][2 * j],     af, vfr[0], vfr[1]);
                        MMA16816(ofr[mt][2 * j + 1], af, vfr[2], vfr[3]);
                    }
                }
            }
        }
    }

    // ---- finalize: normalize and write split output ----
    float inv[4];
    #pragma unroll
    for (int sl = 0; sl < 4; sl++) {
        float l = lrow[sl];
        l += __shfl_xor_sync(0xFFFFFFFFu, l, 1);
        l += __shfl_xor_sync(0xFFFFFFFFu, l, 2);
        inv[sl] = 1.f / l;
    }
    #pragma unroll
    for (int mt = 0; mt < 2; mt++) {
        #pragma unroll
        for (int rr = 0; rr < 2; rr++) {
            const int t = mbase + mt * 16 + (lane >> 2) + rr * 8;
            const float iv = inv[mt * 2 + rr];
            #pragma unroll
            for (int nt = 0; nt < 8; nt++) {
                const int dh = nt * 8 + (lane & 3) * 2;
                const float v0 = ofr[mt][nt][rr * 2] * iv;
                const float v1 = ofr[mt][nt][rr * 2 + 1] * iv;
                const __nv_bfloat16 h0 = __float2bfloat16(v0), h1 = __float2bfloat16(v1);
                const size_t gidx = gbase + (size_t)t * rowstride + dh;
                *(uint32_t*)&Ah_[gidx] = pack_bf2(h0, h1);
                *(uint32_t*)&Al_[gidx] = pack_bf2(__float2bfloat16(v0 - __bfloat162float(h0)),
                                                  __float2bfloat16(v1 - __bfloat162float(h1)));
            }
        }
    }
}

// ---------------- launcher ----------------
extern "C" void kernel_launch(void* const* d_in, const int* in_sizes, int n_in,
                              void* d_out, int out_size)
{
    const float* x      = (const float*)d_in[0];
    const float* Wq_w   = (const float*)d_in[1];
    const float* Wq_b   = (const float*)d_in[2];
    const float* Wv_w   = (const float*)d_in[3];
    const float* Wv_b   = (const float*)d_in[4];
    const float* Wk     = (const float*)d_in[5];
    const float* bk     = (const float*)d_in[6];
    const float* proj_w = (const float*)d_in[7];
    const float* proj_b = (const float*)d_in[8];
    const void*  cid    = d_in[9];
    float* out = (float*)d_out;

    void *pQh, *pQl, *pKh, *pKl, *pVh, *pVl, *pxh, *pxl, *pAh, *pAl;
    void *pwqh, *pwql, *pwvh, *pwvl, *pwph, *pwpl, *pwkth, *pwktl;
    cudaGetSymbolAddress(&pQh, g_Qh);  cudaGetSymbolAddress(&pQl, g_Ql);
    cudaGetSymbolAddress(&pKh, g_Kh);  cudaGetSymbolAddress(&pKl, g_Kl);
    cudaGetSymbolAddress(&pVh, g_Vh);  cudaGetSymbolAddress(&pVl, g_Vl);
    cudaGetSymbolAddress(&pxh, g_xh);  cudaGetSymbolAddress(&pxl, g_xl);
    cudaGetSymbolAddress(&pAh, g_Ah);  cudaGetSymbolAddress(&pAl, g_Al);
    cudaGetSymbolAddress(&pwqh, g_wqh); cudaGetSymbolAddress(&pwql, g_wql);
    cudaGetSymbolAddress(&pwvh, g_wvh); cudaGetSymbolAddress(&pwvl, g_wvl);
    cudaGetSymbolAddress(&pwph, g_wph); cudaGetSymbolAddress(&pwpl, g_wpl);
    cudaGetSymbolAddress(&pwkth, g_wkth); cudaGetSymbolAddress(&pwktl, g_wktl);

    cudaFuncSetAttribute(gemm_mma<false, true>,  cudaFuncAttributeMaxDynamicSharedMemorySize, GEMM_SMEM);
    cudaFuncSetAttribute(gemm_mma<true,  true>,  cudaFuncAttributeMaxDynamicSharedMemorySize, GEMM_SMEM);
    cudaFuncSetAttribute(gemm_mma<false, false>, cudaFuncAttributeMaxDynamicSharedMemorySize, GEMM_SMEM);
    cudaFuncSetAttribute(attn_mma, cudaFuncAttributeMaxDynamicSharedMemorySize, ATTN_SMEM);

    prep_cid<<<1, 32>>>(cid);

    const int n4x = (M_ALL * Dd) / 4;
    conv_split4<<<(n4x + 255) / 256, 256>>>((const float4*)x,
                                            (__nv_bfloat16*)pxh, (__nv_bfloat16*)pxl, n4x);
    const int n4w = (Dd * Dd) / 4;
    conv_split4<<<(n4w + 255) / 256, 256>>>((const float4*)Wq_w,
                                            (__nv_bfloat16*)pwqh, (__nv_bfloat16*)pwql, n4w);
    conv_split4<<<(n4w + 255) / 256, 256>>>((const float4*)Wv_w,
                                            (__nv_bfloat16*)pwvh, (__nv_bfloat16*)pwvl, n4w);
    conv_split4<<<(n4w + 255) / 256, 256>>>((const float4*)proj_w,
                                            (__nv_bfloat16*)pwph, (__nv_bfloat16*)pwpl, n4w);
    conv_wkt<<<(Cc * Dd * Dd + 255) / 256, 256>>>(Wk);

    dim3 gfull(Dd / 128, M_ALL / 128, 1);   // (4, 768)
    dim3 gnode(Dd / 128, BT / 128, Nn);     // (4, 12, 64)

    // Q: pre-scaled by 1/sqrt(DH) = 0.125 (exact power of two)
    gemm_mma<false, true><<<gfull, 256, GEMM_SMEM>>>(
        (const __nv_bfloat16*)pxh, (const __nv_bfloat16*)pxl, Dd,
        (const __nv_bfloat16*)pwqh, (const __nv_bfloat16*)pwql, Wq_b,
        nullptr, (__nv_bfloat16*)pQh, (__nv_bfloat16*)pQl, 0.125f, Dd);
    gemm_mma<false, true><<<gfull, 256, GEMM_SMEM>>>(
        (const __nv_bfloat16*)pxh, (const __nv_bfloat16*)pxl, Dd,
        (const __nv_bfloat16*)pwvh, (const __nv_bfloat16*)pwvl, Wv_b,
        nullptr, (__nv_bfloat16*)pVh, (__nv_bfloat16*)pVl, 1.0f, Dd);
    gemm_mma<true, true><<<gnode, 256, GEMM_SMEM>>>(
        (const __nv_bfloat16*)pxh, (const __nv_bfloat16*)pxl, (long)Nn * Dd,
        (const __nv_bfloat16*)pwkth, (const __nv_bfloat16*)pwktl, bk,
        nullptr, (__nv_bfloat16*)pKh, (__nv_bfloat16*)pKl, 1.0f, (long)Nn * Dd);

    dim3 gattn(Hh, Nn, Bb);
    attn_mma<<<gattn, 192, ATTN_SMEM>>>(
        (const __nv_bfloat16*)pQh, (const __nv_bfloat16*)pQl,
        (const __nv_bfloat16*)pKh, (const __nv_bfloat16*)pKl,
        (const __nv_bfloat16*)pVh, (const __nv_bfloat16*)pVl,
        (__nv_bfloat16*)pAh, (__nv_bfloat16*)pAl);

    gemm_mma<false, false><<<gfull, 256, GEMM_SMEM>>>(
        (const __nv_bfloat16*)pAh, (const __nv_bfloat16*)pAl, Dd,
        (const __nv_bfloat16*)pwph, (const __nv_bfloat16*)pwpl, proj_b,
        out, nullptr, nullptr, 1.0f, Dd);
}

// round 12
// speedup vs baseline: 1.1703x; 1.0508x over previous
#include <cuda_runtime.h>
#include <cuda_bf16.h>
#include <cstdint>

// ---------------- problem constants ----------------
#define Bb   8
#define Tt   192
#define Nn   64
#define Dd   512
#define Hh   8
#define DH   64
#define Cc   8
#define BT   (Bb * Tt)            // 1536
#define M_ALL (Bb * Tt * Nn)      // 98304

#define SWZ(o)   ((o) ^ (((o) >> 3) & 0x70))   // 128-B row swizzle
#define SWZ64(o) ((o) ^ (((o) >> 3) & 0x30))   // 64-B row swizzle

// ---------------- scratch ----------------
__device__ __nv_bfloat16 g_Qh[(size_t)M_ALL * Dd], g_Ql[(size_t)M_ALL * Dd];
__device__ __nv_bfloat16 g_Kh[(size_t)M_ALL * Dd], g_Kl[(size_t)M_ALL * Dd];
__device__ __nv_bfloat16 g_Vh[(size_t)M_ALL * Dd], g_Vl[(size_t)M_ALL * Dd];
__device__ __nv_bfloat16 g_xh[(size_t)M_ALL * Dd], g_xl[(size_t)M_ALL * Dd];
__device__ __nv_bfloat16 g_Ah[(size_t)M_ALL * Dd], g_Al[(size_t)M_ALL * Dd];
__device__ __nv_bfloat16 g_wqh[Dd * Dd], g_wql[Dd * Dd];
__device__ __nv_bfloat16 g_wvh[Dd * Dd], g_wvl[Dd * Dd];
__device__ __nv_bfloat16 g_wph[Dd * Dd], g_wpl[Dd * Dd];
__device__ __nv_bfloat16 g_wkth[(size_t)Cc * Dd * Dd], g_wktl[(size_t)Cc * Dd * Dd];
__device__ int g_cid[Nn];

// ---------------- PTX helpers (portable) ----------------
__device__ __forceinline__ uint32_t smem_u32(const void* p) {
    uint32_t a;
    asm("{ .reg .u64 t; cvta.to.shared.u64 t, %1; cvt.u32.u64 %0, t; }" : "=r"(a) : "l"(p));
    return a;
}
#define CP_ASYNC(dst, src) \
    asm volatile("cp.async.cg.shared.global [%0], [%1], 16;" :: "r"(dst), "l"(src))
#define CP_COMMIT() asm volatile("cp.async.commit_group;" ::: "memory")
#define CP_WAIT(n)  asm volatile("cp.async.wait_group %0;" :: "n"(n) : "memory")

#define LDM_X4(r, addr) \
    asm volatile("ldmatrix.sync.aligned.m8n8.x4.shared.b16 {%0,%1,%2,%3}, [%4];" \
        : "=r"((r)[0]), "=r"((r)[1]), "=r"((r)[2]), "=r"((r)[3]) : "r"(addr))

#define LDM_X4T(r, addr) \
    asm volatile("ldmatrix.sync.aligned.m8n8.x4.trans.shared.b16 {%0,%1,%2,%3}, [%4];" \
        : "=r"((r)[0]), "=r"((r)[1]), "=r"((r)[2]), "=r"((r)[3]) : "r"(addr))

#define MMA16816(d, a, b0, b1) \
    asm volatile("mma.sync.aligned.m16n8k16.row.col.f32.bf16.bf16.f32 " \
        "{%0,%1,%2,%3}, {%4,%5,%6,%7}, {%8,%9}, {%0,%1,%2,%3};" \
        : "+f"((d)[0]), "+f"((d)[1]), "+f"((d)[2]), "+f"((d)[3]) \
        : "r"((a)[0]), "r"((a)[1]), "r"((a)[2]), "r"((a)[3]), "r"(b0), "r"(b1))

__device__ __forceinline__ uint32_t pack_bf2(__nv_bfloat16 lo, __nv_bfloat16 hi) {
    __nv_bfloat162 t(lo, hi);   // .x = lo half (low 16 bits)
    return *(uint32_t*)&t;
}

// ---------------- cluster-id decode ----------------
__global__ void prep_cid(const void* raw) {
    if (threadIdx.x == 0 && blockIdx.x == 0) {
        const int* r32 = (const int*)raw;
        bool is64 = true;
        for (int i = 0; i < 32; i++) {
            int lo = r32[2 * i], hi = r32[2 * i + 1];
            if (hi != 0 || lo < 0 || lo >= Cc) { is64 = false; break; }
        }
        if (is64) {
            const long long* r64 = (const long long*)raw;
            for (int i = 0; i < Nn; i++) g_cid[i] = (int)r64[i];
        } else {
            for (int i = 0; i < Nn; i++) g_cid[i] = r32[i];
        }
    }
}

// ---------------- fp32 -> (hi, lo) bf16 split ----------------
__global__ void conv_split4(const float4* __restrict__ src,
                            __nv_bfloat16* __restrict__ hi,
                            __nv_bfloat16* __restrict__ lo, int n4) {
    int i = blockIdx.x * blockDim.x + threadIdx.x;
    if (i >= n4) return;
    float4 v = src[i];
    __nv_bfloat16 h[4], l[4];
    float vv[4] = {v.x, v.y, v.z, v.w};
    #pragma unroll
    for (int j = 0; j < 4; j++) {
        h[j] = __float2bfloat16(vv[j]);
        l[j] = __float2bfloat16(vv[j] - __bfloat162float(h[j]));
    }
    *(uint2*)&hi[(size_t)i * 4] = *(uint2*)h;
    *(uint2*)&lo[(size_t)i * 4] = *(uint2*)l;
}

__global__ void conv_wkt(const float* __restrict__ Wk) {
    int idx = blockIdx.x * blockDim.x + threadIdx.x;
    if (idx >= Cc * Dd * Dd) return;
    int d = idx % Dd;
    int e = (idx / Dd) % Dd;
    int c = idx / (Dd * Dd);
    float v = Wk[((size_t)c * Dd + d) * Dd + e];
    __nv_bfloat16 h = __float2bfloat16(v);
    g_wkth[idx] = h;
    g_wktl[idx] = __float2bfloat16(v - __bfloat162float(h));
}

// ---------------- mma.sync split-bf16 GEMM ----------------
// CTA tile 128x128, warp tile 64x32 (8 warps). K chunks of 32 (64-B smem rows,
// SW64 swizzle), 3-stage cp.async pipeline, ONE sync per chunk, occupancy 2.
// Stage layout: A-hi(8K) A-lo(8K) B-hi(8K) B-lo(8K) = 32 KB; 3 stages = 96 KB.
#define PLANE 8192
#define STAGE_B 32768
#define GEMM_SMEM (3 * STAGE_B)          // 98304

// SPLIT: write hi/lo bf16 planes (scaled); else fp32.
template<bool NODE, bool SPLIT>
__global__ __launch_bounds__(256, 2)
void gemm_mma(const __nv_bfloat16* __restrict__ Ah, const __nv_bfloat16* __restrict__ Al,
              long lda,
              const __nv_bfloat16* __restrict__ Wh, const __nv_bfloat16* __restrict__ Wl,
              const float* __restrict__ bias,
              float* __restrict__ Cf,
              __nv_bfloat16* __restrict__ Ch, __nv_bfloat16* __restrict__ Cl,
              float scale, long ldc)
{
    extern __shared__ char smem[];
    const uint32_t sb = smem_u32(smem);
    const int tid = threadIdx.x;
    const int wid = tid >> 5;
    const int lane = tid & 31;
    const int wm = wid >> 2;        // 0..1 -> 64-row slab
    const int wn = wid & 3;         // 0..3 -> 32-col slab

    size_t aoff = 0, woff = 0, boff = 0, coff = 0;
    if (NODE) {
        const int nn = blockIdx.z;
        const int cc = g_cid[nn];
        aoff = (size_t)nn * Dd;
        coff = aoff;
        woff = (size_t)cc * Dd * Dd;
        boff = (size_t)cc * Dd;
    }
    const int m0 = blockIdx.y * 128;
    const int n0 = blockIdx.x * 128;

    float acc[4][4][4];
    #pragma unroll
    for (int i = 0; i < 4; i++)
        #pragma unroll
        for (int j = 0; j < 4; j++)
            #pragma unroll
            for (int k = 0; k < 4; k++) acc[i][j][k] = 0.f;

    const int NC = Dd / 32;   // 16 chunks

    // chunk loader: 128 rows x 32 cols per plane, 64-B rows, SW64
    auto load_chunk = [&](int ci) {
        const int stg = ci % 3;
        const int koff = ci * 32;
        const uint32_t sS = sb + stg * STAGE_B;
        #pragma unroll
        for (int t = 0; t < 2; t++) {
            const int idx = tid + t * 256;        // 0..511
            const int row = idx >> 2;
            const int c   = idx & 3;
            const uint32_t so = SWZ64((uint32_t)(row * 64 + c * 16));
            const size_t ga = (size_t)(m0 + row) * lda + aoff + koff + c * 8;
            CP_ASYNC(sS + so,         &Ah[ga]);
            CP_ASYNC(sS + PLANE + so, &Al[ga]);
            const size_t gb = (size_t)(n0 + row) * Dd + woff + koff + c * 8;
            CP_ASYNC(sS + 2 * PLANE + so, &Wh[gb]);
            CP_ASYNC(sS + 3 * PLANE + so, &Wl[gb]);
        }
        CP_COMMIT();
    };

    load_chunk(0);
    load_chunk(1);

    const int ar = lane & 15, ag = lane >> 4;
    const int br = lane & 7,  bg = lane >> 3;

    for (int ci = 0; ci < NC; ci++) {
        if (ci < NC - 1) { CP_WAIT(1); }
        else             { CP_WAIT(0); }
        __syncthreads();
        if (ci + 2 < NC) load_chunk(ci + 2);

        const int stg = ci % 3;
        const uint32_t sAh = sb + stg * STAGE_B;
        const uint32_t sAl = sAh + PLANE;
        const uint32_t sBh = sAh + 2 * PLANE;
        const uint32_t sBl = sAh + 3 * PLANE;

        #pragma unroll
        for (int ks = 0; ks < 2; ks++) {
            uint32_t ah[4][4];
            #pragma unroll
            for (int im = 0; im < 4; im++) {
                const uint32_t off = SWZ64((uint32_t)(
                    (wm * 64 + im * 16 + ar) * 64 + ks * 32 + ag * 16));
                LDM_X4(ah[im], sAh + off);
            }
            uint32_t bh[2][4], bl[2][4];
            #pragma unroll
            for (int ib = 0; ib < 2; ib++) {
                const uint32_t off = SWZ64((uint32_t)(
                    (wn * 32 + ib * 16 + (bg >> 1) * 8 + br) * 64 + ks * 32 + (bg & 1) * 16));
                LDM_X4(bh[ib], sBh + off);
                LDM_X4(bl[ib], sBl + off);
            }
            // ---- pass hh ----
            #pragma unroll
            for (int im = 0; im < 4; im++)
                #pragma unroll
                for (int in = 0; in < 4; in++)
                    MMA16816(acc[im][in], ah[im],
                             bh[in >> 1][(in & 1) * 2 + 0], bh[in >> 1][(in & 1) * 2 + 1]);
            // ---- pass hl ----
            #pragma unroll
            for (int im = 0; im < 4; im++)
                #pragma unroll
                for (int in = 0; in < 4; in++)
                    MMA16816(acc[im][in], ah[im],
                             bl[in >> 1][(in & 1) * 2 + 0], bl[in >> 1][(in & 1) * 2 + 1]);
            // ---- pass lh (load A-lo late; bl registers are dead now) ----
            uint32_t al[4][4];
            #pragma unroll
            for (int im = 0; im < 4; im++) {
                const uint32_t off = SWZ64((uint32_t)(
                    (wm * 64 + im * 16 + ar) * 64 + ks * 32 + ag * 16));
                LDM_X4(al[im], sAl + off);
            }
            #pragma unroll
            for (int im = 0; im < 4; im++)
                #pragma unroll
                for (int in = 0; in < 4; in++)
                    MMA16816(acc[im][in], al[im],
                             bh[in >> 1][(in & 1) * 2 + 0], bh[in >> 1][(in & 1) * 2 + 1]);
        }
    }
    __syncthreads();

    // ---- epilogue ----
    const int rbase = m0 + wm * 64 + (lane >> 2);
    const int cbase = n0 + wn * 32 + (lane & 3) * 2;
    #pragma unroll
    for (int im = 0; im < 4; im++) {
        #pragma unroll
        for (int in = 0; in < 4; in++) {
            const int cg = cbase + in * 8;
            const float b0 = bias[boff + cg], b1 = bias[boff + cg + 1];
            const int r0 = rbase + im * 16;
            float v0 = acc[im][in][0] + b0, v1 = acc[im][in][1] + b1;
            float v2 = acc[im][in][2] + b0, v3 = acc[im][in][3] + b1;
            if (SPLIT) {
                v0 *= scale; v1 *= scale; v2 *= scale; v3 *= scale;
                __nv_bfloat16 h0 = __float2bfloat16(v0), h1 = __float2bfloat16(v1);
                __nv_bfloat16 h2 = __float2bfloat16(v2), h3 = __float2bfloat16(v3);
                __nv_bfloat16 l0 = __float2bfloat16(v0 - __bfloat162float(h0));
                __nv_bfloat16 l1 = __float2bfloat16(v1 - __bfloat162float(h1));
                __nv_bfloat16 l2 = __float2bfloat16(v2 - __bfloat162float(h2));
                __nv_bfloat16 l3 = __float2bfloat16(v3 - __bfloat162float(h3));
                *(uint32_t*)&Ch[(size_t)r0 * ldc + coff + cg]       = pack_bf2(h0, h1);
                *(uint32_t*)&Cl[(size_t)r0 * ldc + coff + cg]       = pack_bf2(l0, l1);
                *(uint32_t*)&Ch[(size_t)(r0 + 8) * ldc + coff + cg] = pack_bf2(h2, h3);
                *(uint32_t*)&Cl[(size_t)(r0 + 8) * ldc + coff + cg] = pack_bf2(l2, l3);
            } else {
                *(float2*)&Cf[(size_t)r0 * ldc + coff + cg]       = make_float2(v0, v1);
                *(float2*)&Cf[(size_t)(r0 + 8) * ldc + coff + cg] = make_float2(v2, v3);
            }
        }
    }
}

// ---------------- tensor-core flash attention ----------------
// One CTA per (b,n,h). 6 warps x 32 rows. S = Q*K^T (3-term split, Q pre-scaled),
// online softmax in fragments, out = P*V (3-term: ph*Vh + ph*Vl + pl*Vh).
#define PL 24576                          // one 192x64 bf16 plane, swizzled
#define ATTN_SMEM (6 * PL)                // 147456

__global__ __launch_bounds__(192, 1)
void attn_mma(const __nv_bfloat16* __restrict__ Qh_, const __nv_bfloat16* __restrict__ Ql_,
              const __nv_bfloat16* __restrict__ Kh_, const __nv_bfloat16* __restrict__ Kl_,
              const __nv_bfloat16* __restrict__ Vh_, const __nv_bfloat16* __restrict__ Vl_,
              __nv_bfloat16* __restrict__ Ah_, __nv_bfloat16* __restrict__ Al_)
{
    extern __shared__ char smem[];
    const uint32_t sb = smem_u32(smem);
    const int h = blockIdx.x, n = blockIdx.y, b = blockIdx.z;
    const int tid = threadIdx.x, wid = tid >> 5, lane = tid & 31;
    const size_t rowstride = (size_t)Nn * Dd;
    const size_t gbase = ((size_t)(b * Tt) * Nn + n) * Dd + (size_t)h * DH;

    // ---- load 6 planes into smem (swizzled 128B rows) ----
    {
        const __nv_bfloat16* srcs[6] = {Qh_ + gbase, Ql_ + gbase, Kh_ + gbase,
                                        Kl_ + gbase, Vh_ + gbase, Vl_ + gbase};
        #pragma unroll
        for (int p = 0; p < 6; p++) {
            const __nv_bfloat16* src = srcs[p];
            #pragma unroll
            for (int it = 0; it < 8; it++) {
                const int idx = tid + it * 192;     // 0..1535
                const int row = idx >> 3, g = idx & 7;
                *(uint4*)(smem + p * PL + SWZ(row * 128 + g * 16)) =
                    *(const uint4*)&src[(size_t)row * rowstride + g * 8];
            }
        }
    }
    __syncthreads();

    const int mbase = wid * 32;
    float mrow[4] = {-1e30f, -1e30f, -1e30f, -1e30f};   // slot = mt*2 + (elpair)
    float lrow[4] = {0.f, 0.f, 0.f, 0.f};
    float ofr[2][8][4];
    #pragma unroll
    for (int a = 0; a < 2; a++)
        #pragma unroll
        for (int c = 0; c < 8; c++)
            #pragma unroll
            for (int e = 0; e < 4; e++) ofr[a][c][e] = 0.f;

    const int ar = lane & 15, ag = lane >> 4;
    const int br = lane & 7,  bg = lane >> 3;

    for (int sb3 = 0; sb3 < 3; sb3++) {
        // ---- S = Q K^T over 64 s-cols (8 n-tiles), 3 passes ----
        float sfr[2][8][4];
        #pragma unroll
        for (int a = 0; a < 2; a++)
            #pragma unroll
            for (int c = 0; c < 8; c++)
                #pragma unroll
                for (int e = 0; e < 4; e++) sfr[a][c][e] = 0.f;

        #pragma unroll
        for (int p = 0; p < 3; p++) {
            const uint32_t qs = sb + ((p < 2) ? 0 : 1) * PL;
            const uint32_t ks_ = sb + ((p == 1) ? 3 : 2) * PL;
            #pragma unroll
            for (int ks = 0; ks < 4; ks++) {
                uint32_t afr[2][4];
                #pragma unroll
                for (int mt = 0; mt < 2; mt++)
                    LDM_X4(afr[mt], qs + SWZ((uint32_t)(
                        (mbase + mt * 16 + ar) * 128 + ks * 32 + ag * 16)));
                #pragma unroll
                for (int ib = 0; ib < 4; ib++) {
                    uint32_t bfr[4];
                    LDM_X4(bfr, ks_ + SWZ((uint32_t)(
                        (sb3 * 64 + ib * 16 + (bg >> 1) * 8 + br) * 128 + ks * 32 + (bg & 1) * 16)));
                    #pragma unroll
                    for (int mt = 0; mt < 2; mt++) {
                        MMA16816(sfr[mt][2 * ib],     afr[mt], bfr[0], bfr[1]);
                        MMA16816(sfr[mt][2 * ib + 1], afr[mt], bfr[2], bfr[3]);
                    }
                }
            }
        }

        // ---- online softmax ----
        float alpha[4];
        #pragma unroll
        for (int sl = 0; sl < 4; sl++) {
            const int mt = sl >> 1, rr = sl & 1;
            float mx = -1e30f;
            #pragma unroll
            for (int nt = 0; nt < 8; nt++)
                mx = fmaxf(mx, fmaxf(sfr[mt][nt][rr * 2], sfr[mt][nt][rr * 2 + 1]));
            mx = fmaxf(mx, __shfl_xor_sync(0xFFFFFFFFu, mx, 1));
            mx = fmaxf(mx, __shfl_xor_sync(0xFFFFFFFFu, mx, 2));
            const float mn = fmaxf(mrow[sl], mx);
            alpha[sl] = __expf(mrow[sl] - mn);
            mrow[sl] = mn;
            lrow[sl] *= alpha[sl];
        }
        #pragma unroll
        for (int mt = 0; mt < 2; mt++)
            #pragma unroll
            for (int nt = 0; nt < 8; nt++) {
                ofr[mt][nt][0] *= alpha[mt * 2];     ofr[mt][nt][1] *= alpha[mt * 2];
                ofr[mt][nt][2] *= alpha[mt * 2 + 1]; ofr[mt][nt][3] *= alpha[mt * 2 + 1];
            }

        // P = exp(S - m), split to (ph, pl) packed as A-fragment halves
        uint32_t ph[2][8][2], pl[2][8][2];
        #pragma unroll
        for (int mt = 0; mt < 2; mt++) {
            #pragma unroll
            for (int nt = 0; nt < 8; nt++) {
                const float p0 = __expf(sfr[mt][nt][0] - mrow[mt * 2]);
                const float p1 = __expf(sfr[mt][nt][1] - mrow[mt * 2]);
                const float p2 = __expf(sfr[mt][nt][2] - mrow[mt * 2 + 1]);
                const float p3 = __expf(sfr[mt][nt][3] - mrow[mt * 2 + 1]);
                lrow[mt * 2]     += p0 + p1;
                lrow[mt * 2 + 1] += p2 + p3;
                const __nv_bfloat16 h0 = __float2bfloat16(p0), h1 = __float2bfloat16(p1);
                const __nv_bfloat16 h2 = __float2bfloat16(p2), h3 = __float2bfloat16(p3);
                ph[mt][nt][0] = pack_bf2(h0, h1);
                ph[mt][nt][1] = pack_bf2(h2, h3);
                pl[mt][nt][0] = pack_bf2(__float2bfloat16(p0 - __bfloat162float(h0)),
                                         __float2bfloat16(p1 - __bfloat162float(h1)));
                pl[mt][nt][1] = pack_bf2(__float2bfloat16(p2 - __bfloat162float(h2)),
                                         __float2bfloat16(p3 - __bfloat162float(h3)));
            }
        }

        // ---- out += P * V : passes (ph,Vh), (ph,Vl), (pl,Vh) ----
        const int g = lane >> 3;
        #pragma unroll
        for (int q = 0; q < 3; q++) {
            const uint32_t vs = sb + ((q == 1) ? 5 : 4) * PL;
            #pragma unroll
            for (int ks2 = 0; ks2 < 4; ks2++) {
                #pragma unroll
                for (int j = 0; j < 4; j++) {
                    uint32_t vfr[4];
                    const int srow = sb3 * 64 + ks2 * 16 + (g & 1) * 8 + (lane & 7);
                    const int gran = 2 * j + (g >> 1);
                    LDM_X4T(vfr, vs + SWZ((uint32_t)(srow * 128 + gran * 16)));
                    #pragma unroll
                    for (int mt = 0; mt < 2; mt++) {
                        uint32_t af[4];
                        if (q == 2) {
                            af[0] = pl[mt][2 * ks2][0];     af[1] = pl[mt][2 * ks2][1];
                            af[2] = pl[mt][2 * ks2 + 1][0]; af[3] = pl[mt][2 * ks2 + 1][1];
                        } else {
                            af[0] = ph[mt][2 * ks2][0];     af[1] = ph[mt][2 * ks2][1];
                            af[2] = ph[mt][2 * ks2 + 1][0]; af[3] = ph[mt][2 * ks2 + 1][1];
                        }
                        MMA16816(ofr[mt][2 * j],     af, vfr[0], vfr[1]);
                        MMA16816(ofr[mt][2 * j + 1], af, vfr[2], vfr[3]);
                    }
                }
            }
        }
    }

    // ---- finalize: normalize and write split output ----
    float inv[4];
    #pragma unroll
    for (int sl = 0; sl < 4; sl++) {
        float l = lrow[sl];
        l += __shfl_xor_sync(0xFFFFFFFFu, l, 1);
        l += __shfl_xor_sync(0xFFFFFFFFu, l, 2);
        inv[sl] = 1.f / l;
    }
    #pragma unroll
    for (int mt = 0; mt < 2; mt++) {
        #pragma unroll
        for (int rr = 0; rr < 2; rr++) {
            const int t = mbase + mt * 16 + (lane >> 2) + rr * 8;
            const float iv = inv[mt * 2 + rr];
            #pragma unroll
            for (int nt = 0; nt < 8; nt++) {
                const int dh = nt * 8 + (lane & 3) * 2;
                const float v0 = ofr[mt][nt][rr * 2] * iv;
                const float v1 = ofr[mt][nt][rr * 2 + 1] * iv;
                const __nv_bfloat16 h0 = __float2bfloat16(v0), h1 = __float2bfloat16(v1);
                const size_t gidx = gbase + (size_t)t * rowstride + dh;
                *(uint32_t*)&Ah_[gidx] = pack_bf2(h0, h1);
                *(uint32_t*)&Al_[gidx] = pack_bf2(__float2bfloat16(v0 - __bfloat162float(h0)),
                                                  __float2bfloat16(v1 - __bfloat162float(h1)));
            }
        }
    }
}

// ---------------- launcher ----------------
extern "C" void kernel_launch(void* const* d_in, const int* in_sizes, int n_in,
                              void* d_out, int out_size)
{
    const float* x      = (const float*)d_in[0];
    const float* Wq_w   = (const float*)d_in[1];
    const float* Wq_b   = (const float*)d_in[2];
    const float* Wv_w   = (const float*)d_in[3];
    const float* Wv_b   = (const float*)d_in[4];
    const float* Wk     = (const float*)d_in[5];
    const float* bk     = (const float*)d_in[6];
    const float* proj_w = (const float*)d_in[7];
    const float* proj_b = (const float*)d_in[8];
    const void*  cid    = d_in[9];
    float* out = (float*)d_out;

    void *pQh, *pQl, *pKh, *pKl, *pVh, *pVl, *pxh, *pxl, *pAh, *pAl;
    void *pwqh, *pwql, *pwvh, *pwvl, *pwph, *pwpl, *pwkth, *pwktl;
    cudaGetSymbolAddress(&pQh, g_Qh);  cudaGetSymbolAddress(&pQl, g_Ql);
    cudaGetSymbolAddress(&pKh, g_Kh);  cudaGetSymbolAddress(&pKl, g_Kl);
    cudaGetSymbolAddress(&pVh, g_Vh);  cudaGetSymbolAddress(&pVl, g_Vl);
    cudaGetSymbolAddress(&pxh, g_xh);  cudaGetSymbolAddress(&pxl, g_xl);
    cudaGetSymbolAddress(&pAh, g_Ah);  cudaGetSymbolAddress(&pAl, g_Al);
    cudaGetSymbolAddress(&pwqh, g_wqh); cudaGetSymbolAddress(&pwql, g_wql);
    cudaGetSymbolAddress(&pwvh, g_wvh); cudaGetSymbolAddress(&pwvl, g_wvl);
    cudaGetSymbolAddress(&pwph, g_wph); cudaGetSymbolAddress(&pwpl, g_wpl);
    cudaGetSymbolAddress(&pwkth, g_wkth); cudaGetSymbolAddress(&pwktl, g_wktl);

    cudaFuncSetAttribute(gemm_mma<false, true>,  cudaFuncAttributeMaxDynamicSharedMemorySize, GEMM_SMEM);
    cudaFuncSetAttribute(gemm_mma<true,  true>,  cudaFuncAttributeMaxDynamicSharedMemorySize, GEMM_SMEM);
    cudaFuncSetAttribute(gemm_mma<false, false>, cudaFuncAttributeMaxDynamicSharedMemorySize, GEMM_SMEM);
    cudaFuncSetAttribute(attn_mma, cudaFuncAttributeMaxDynamicSharedMemorySize, ATTN_SMEM);

    prep_cid<<<1, 32>>>(cid);

    const int n4x = (M_ALL * Dd) / 4;
    conv_split4<<<(n4x + 255) / 256, 256>>>((const float4*)x,
                                            (__nv_bfloat16*)pxh, (__nv_bfloat16*)pxl, n4x);
    const int n4w = (Dd * Dd) / 4;
    conv_split4<<<(n4w + 255) / 256, 256>>>((const float4*)Wq_w,
                                            (__nv_bfloat16*)pwqh, (__nv_bfloat16*)pwql, n4w);
    conv_split4<<<(n4w + 255) / 256, 256>>>((const float4*)Wv_w,
                                            (__nv_bfloat16*)pwvh, (__nv_bfloat16*)pwvl, n4w);
    conv_split4<<<(n4w + 255) / 256, 256>>>((const float4*)proj_w,
                                            (__nv_bfloat16*)pwph, (__nv_bfloat16*)pwpl, n4w);
    conv_wkt<<<(Cc * Dd * Dd + 255) / 256, 256>>>(Wk);

    dim3 gfull(Dd / 128, M_ALL / 128, 1);   // (4, 768)
    dim3 gnode(Dd / 128, BT / 128, Nn);     // (4, 12, 64)

    // Q: pre-scaled by 1/sqrt(DH) = 0.125 (exact power of two)
    gemm_mma<false, true><<<gfull, 256, GEMM_SMEM>>>(
        (const __nv_bfloat16*)pxh, (const __nv_bfloat16*)pxl, Dd,
        (const __nv_bfloat16*)pwqh, (const __nv_bfloat16*)pwql, Wq_b,
        nullptr, (__nv_bfloat16*)pQh, (__nv_bfloat16*)pQl, 0.125f, Dd);
    gemm_mma<false, true><<<gfull, 256, GEMM_SMEM>>>(
        (const __nv_bfloat16*)pxh, (const __nv_bfloat16*)pxl, Dd,
        (const __nv_bfloat16*)pwvh, (const __nv_bfloat16*)pwvl, Wv_b,
        nullptr, (__nv_bfloat16*)pVh, (__nv_bfloat16*)pVl, 1.0f, Dd);
    gemm_mma<true, true><<<gnode, 256, GEMM_SMEM>>>(
        (const __nv_bfloat16*)pxh, (const __nv_bfloat16*)pxl, (long)Nn * Dd,
        (const __nv_bfloat16*)pwkth, (const __nv_bfloat16*)pwktl, bk,
        nullptr, (__nv_bfloat16*)pKh, (__nv_bfloat16*)pKl, 1.0f, (long)Nn * Dd);

    dim3 gattn(Hh, Nn, Bb);
    attn_mma<<<gattn, 192, ATTN_SMEM>>>(
        (const __nv_bfloat16*)pQh, (const __nv_bfloat16*)pQl,
        (const __nv_bfloat16*)pKh, (const __nv_bfloat16*)pKl,
        (const __nv_bfloat16*)pVh, (const __nv_bfloat16*)pVl,
        (__nv_bfloat16*)pAh, (__nv_bfloat16*)pAl);

    gemm_mma<false, false><<<gfull, 256, GEMM_SMEM>>>(
        (const __nv_bfloat16*)pAh, (const __nv_bfloat16*)pAl, Dd,
        (const __nv_bfloat16*)pwph, (const __nv_bfloat16*)pwpl, proj_b,
        out, nullptr, nullptr, 1.0f, Dd);
}